// round 16
// baseline (speedup 1.0000x reference)
#include <cuda_runtime.h>
#include <cuda_bf16.h>

#define NN 8192
#define EE 262144
#define FIN 64
#define HIDD 128
#define LATD 64
#define NH 4
#define DHD 16
#define KSPLIT 8

typedef unsigned int uint;

// ---------------- scratch (device globals; no allocations allowed) ----------
__device__ int   g_count[NN];
__device__ int   g_rowptr[NN + 1];
__device__ int   g_fill[NN];
__device__ float g_dis[NN];
__device__ int2  g_csr[EE];          // packed (src, norm-bits) per edge

__device__ float g_G[NN * HIDD];     // gemm/agg scratch
__device__ float g_bufA[NN * HIDD];  // ping
__device__ float g_bufB[NN * HIDD];  // pong
__device__ __nv_bfloat16 g_qkvh[NN * 3 * LATD];  // q,k bf16 (q pre-scaled); v f16
__device__ float g_attO[KSPLIT * NN * LATD];     // partial PV sums (raw)
__device__ float g_attL[KSPLIT * NN * NH];       // partial softmax denoms

// pre-converted weights (bf16 split hi/lo), concatenated:
// e1[64x128]@0  e2[128x128]@8192  e3@24576  e4[128x64]@40960
// d1[64x128]@49152  d2@57344  d3@73728  d4[128x64]@90112   total 98304
#define WTOT 98304
__device__ __nv_bfloat16 g_whi[WTOT];
__device__ __nv_bfloat16 g_wlo[WTOT];

// ---------------- fast math helpers ----------------------------------------
__device__ __forceinline__ float fast_rsqrt(float x) {
    float y;
    asm("rsqrt.approx.f32 %0, %1;" : "=f"(y) : "f"(x));
    return y;
}
__device__ __forceinline__ uint cvt_bf16x2(float lo, float hi) {
    uint r;
    asm("cvt.rn.bf16x2.f32 %0, %1, %2;" : "=r"(r) : "f"(hi), "f"(lo));
    return r;
}
__device__ __forceinline__ uint cvt_f16x2(float lo, float hi) {
    uint r;
    asm("cvt.rn.f16x2.f32 %0, %1, %2;" : "=r"(r) : "f"(hi), "f"(lo));
    return r;
}
__device__ __forceinline__ uint ex2_f16x2(uint x) {
    uint y;
    asm("ex2.approx.f16x2 %0, %1;" : "=r"(y) : "r"(x));
    return y;
}

// ---------------- mma / ldmatrix helpers ------------------------------------
__device__ __forceinline__ void ldm4(uint& r0, uint& r1, uint& r2, uint& r3, uint addr) {
    asm volatile("ldmatrix.sync.aligned.m8n8.x4.shared.b16 {%0,%1,%2,%3}, [%4];"
                 : "=r"(r0), "=r"(r1), "=r"(r2), "=r"(r3) : "r"(addr));
}
__device__ __forceinline__ void ldm4t(uint& r0, uint& r1, uint& r2, uint& r3, uint addr) {
    asm volatile("ldmatrix.sync.aligned.m8n8.x4.trans.shared.b16 {%0,%1,%2,%3}, [%4];"
                 : "=r"(r0), "=r"(r1), "=r"(r2), "=r"(r3) : "r"(addr));
}
__device__ __forceinline__ void mma16816_bf16(float& c0, float& c1, float& c2, float& c3,
                                              uint a0, uint a1, uint a2, uint a3,
                                              uint b0, uint b1) {
    asm volatile("mma.sync.aligned.m16n8k16.row.col.f32.bf16.bf16.f32 "
                 "{%0,%1,%2,%3}, {%4,%5,%6,%7}, {%8,%9}, {%0,%1,%2,%3};"
                 : "+f"(c0), "+f"(c1), "+f"(c2), "+f"(c3)
                 : "r"(a0), "r"(a1), "r"(a2), "r"(a3), "r"(b0), "r"(b1));
}
__device__ __forceinline__ void mma16816_f16(float& c0, float& c1, float& c2, float& c3,
                                             uint a0, uint a1, uint a2, uint a3,
                                             uint b0, uint b1) {
    asm volatile("mma.sync.aligned.m16n8k16.row.col.f32.f16.f16.f32 "
                 "{%0,%1,%2,%3}, {%4,%5,%6,%7}, {%8,%9}, {%0,%1,%2,%3};"
                 : "+f"(c0), "+f"(c1), "+f"(c2), "+f"(c3)
                 : "r"(a0), "r"(a1), "r"(a2), "r"(a3), "r"(b0), "r"(b1));
}

// ---------------- CSR build -------------------------------------------------
__global__ void k_hist(const int* __restrict__ ei) {
    int e = blockIdx.x * blockDim.x + threadIdx.x;
    if (e < EE) atomicAdd(&g_count[ei[EE + e]], 1);
}

__global__ void k_scan() {
    __shared__ int s[1024];
    int tid = threadIdx.x;
    int base = tid * 8;
    int local[8];
    int sum = 0;
#pragma unroll
    for (int i = 0; i < 8; i++) { local[i] = g_count[base + i]; sum += local[i]; }
    s[tid] = sum;
    __syncthreads();
    for (int off = 1; off < 1024; off <<= 1) {
        int v = 0;
        if (tid >= off) v = s[tid - off];
        __syncthreads();
        s[tid] += v;
        __syncthreads();
    }
    int run = s[tid] - sum;  // exclusive base
#pragma unroll
    for (int i = 0; i < 8; i++) {
        g_rowptr[base + i] = run;
        g_fill[base + i]   = run;
        g_dis[base + i]    = fast_rsqrt((float)local[i] + 1.0f);
        run += local[i];
    }
    if (tid == 1023) g_rowptr[NN] = run;
}

__global__ void k_build(const int* __restrict__ ei) {
    int e = blockIdx.x * blockDim.x + threadIdx.x;
    if (e < EE) {
        int s = ei[e];
        int d = ei[EE + e];
        int pos = atomicAdd(&g_fill[d], 1);
        g_csr[pos] = make_int2(s, __float_as_int(g_dis[s] * g_dis[d]));
    }
}

// ---------------- weight conversion: fp32 -> bf16 hi/lo (once per launch) ---
__global__ void k_wconv(const float* __restrict__ w_e1, const float* __restrict__ w_e2,
                        const float* __restrict__ w_e3, const float* __restrict__ w_e4,
                        const float* __restrict__ w_d1, const float* __restrict__ w_d2,
                        const float* __restrict__ w_d3, const float* __restrict__ w_d4) {
    int i = blockIdx.x * blockDim.x + threadIdx.x;
    if (i >= WTOT) return;
    const float* src;
    int off;
    if      (i < 8192)  { src = w_e1; off = 0; }
    else if (i < 24576) { src = w_e2; off = 8192; }
    else if (i < 40960) { src = w_e3; off = 24576; }
    else if (i < 49152) { src = w_e4; off = 40960; }
    else if (i < 57344) { src = w_d1; off = 49152; }
    else if (i < 73728) { src = w_d2; off = 57344; }
    else if (i < 90112) { src = w_d3; off = 73728; }
    else                { src = w_d4; off = 90112; }
    float v = src[i - off];
    __nv_bfloat16 h = __float2bfloat16(v);
    g_whi[i] = h;
    g_wlo[i] = __float2bfloat16(v - __bfloat162float(h));
}

// ---------------- HMMA GEMM: Y = X @ W (+bias+relu), bf16x3 split -----------
template <int DIN, int DOUT, bool BIASRELU>
__global__ void __launch_bounds__(256)
k_gemm_mma(const float* __restrict__ X, const __nv_bfloat16* __restrict__ Whi,
           const __nv_bfloat16* __restrict__ Wlo, const float* __restrict__ bias,
           float* __restrict__ Y) {
    constexpr int NWN = DOUT / 64;        // 2 or 1
    constexpr int NWM = 8 / NWN;          // 4 or 8
    constexpr int MT  = NWM * 16;         // 64 or 128
    constexpr int PX  = 80;               // bytes/row of 32-k X chunk (64+16)
    constexpr int PW  = DOUT * 2 + 16;    // 272 or 144

    __shared__ __align__(16) char sXhi[MT * PX];
    __shared__ __align__(16) char sXlo[MT * PX];
    __shared__ __align__(16) char sWhi[32 * PW];
    __shared__ __align__(16) char sWlo[32 * PW];

    int t = threadIdx.x;
    int w = t >> 5, l = t & 31;
    int wm = w % NWM, wn = w / NWM;
    int rowbase = blockIdx.x * MT;

    float c[8][4];
#pragma unroll
    for (int i = 0; i < 8; i++) {
        c[i][0] = 0.f; c[i][1] = 0.f; c[i][2] = 0.f; c[i][3] = 0.f;
    }

    uint sXhiB = (uint)__cvta_generic_to_shared(sXhi);
    uint sXloB = (uint)__cvta_generic_to_shared(sXlo);
    uint sWhiB = (uint)__cvta_generic_to_shared(sWhi);
    uint sWloB = (uint)__cvta_generic_to_shared(sWlo);

    int r8 = l & 7;
    uint aoffc = (uint)(wm * 16 + ((l >> 3) & 1) * 8 + r8) * PX + ((l >> 4) & 1) * 16;
    uint boffc = (uint)(((l >> 3) & 1) * 8 + r8) * PW + wn * 128 + ((l >> 4) & 1) * 16;

    for (int kc = 0; kc < DIN; kc += 32) {
        constexpr int WTASK = 32 * DOUT / 8;
        for (int id = t; id < WTASK; id += 256) {
            int r = id / (DOUT / 8), c8 = id % (DOUT / 8);
            uint4 vh = *reinterpret_cast<const uint4*>(Whi + (kc + r) * DOUT + c8 * 8);
            uint4 vl = *reinterpret_cast<const uint4*>(Wlo + (kc + r) * DOUT + c8 * 8);
            *reinterpret_cast<uint4*>(sWhi + r * PW + c8 * 16) = vh;
            *reinterpret_cast<uint4*>(sWlo + r * PW + c8 * 16) = vl;
        }
        for (int id = t; id < MT * 8; id += 256) {
            int r = id >> 3, g4 = id & 7;
            float4 xv = *reinterpret_cast<const float4*>(X + (size_t)(rowbase + r) * DIN + kc + g4 * 4);
            float h0 = __bfloat162float(__float2bfloat16(xv.x));
            float h1 = __bfloat162float(__float2bfloat16(xv.y));
            float h2 = __bfloat162float(__float2bfloat16(xv.z));
            float h3 = __bfloat162float(__float2bfloat16(xv.w));
            uint2 hp = make_uint2(cvt_bf16x2(xv.x, xv.y), cvt_bf16x2(xv.z, xv.w));
            uint2 lp = make_uint2(cvt_bf16x2(xv.x - h0, xv.y - h1),
                                  cvt_bf16x2(xv.z - h2, xv.w - h3));
            *reinterpret_cast<uint2*>(sXhi + r * PX + g4 * 8) = hp;
            *reinterpret_cast<uint2*>(sXlo + r * PX + g4 * 8) = lp;
        }
        __syncthreads();
#pragma unroll
        for (int ks = 0; ks < 2; ks++) {
            uint ah0, ah1, ah2, ah3, al0, al1, al2, al3;
            ldm4(ah0, ah1, ah2, ah3, sXhiB + aoffc + ks * 32);
            ldm4(al0, al1, al2, al3, sXloB + aoffc + ks * 32);
#pragma unroll
            for (int nb2 = 0; nb2 < 4; nb2++) {
                uint bo = boffc + (uint)ks * 16 * PW + nb2 * 32;
                uint bh0, bh1, bh2, bh3, bl0, bl1, bl2, bl3;
                ldm4t(bh0, bh1, bh2, bh3, sWhiB + bo);
                ldm4t(bl0, bl1, bl2, bl3, sWloB + bo);
                int nb = nb2 * 2;
                mma16816_bf16(c[nb][0], c[nb][1], c[nb][2], c[nb][3],
                              ah0, ah1, ah2, ah3, bh0, bh1);
                mma16816_bf16(c[nb][0], c[nb][1], c[nb][2], c[nb][3],
                              ah0, ah1, ah2, ah3, bl0, bl1);
                mma16816_bf16(c[nb][0], c[nb][1], c[nb][2], c[nb][3],
                              al0, al1, al2, al3, bh0, bh1);
                mma16816_bf16(c[nb + 1][0], c[nb + 1][1], c[nb + 1][2], c[nb + 1][3],
                              ah0, ah1, ah2, ah3, bh2, bh3);
                mma16816_bf16(c[nb + 1][0], c[nb + 1][1], c[nb + 1][2], c[nb + 1][3],
                              ah0, ah1, ah2, ah3, bl2, bl3);
                mma16816_bf16(c[nb + 1][0], c[nb + 1][1], c[nb + 1][2], c[nb + 1][3],
                              al0, al1, al2, al3, bh2, bh3);
            }
        }
        __syncthreads();
    }

    int g = l >> 2, tt = l & 3;
    int row0 = rowbase + wm * 16 + g;
#pragma unroll
    for (int nb = 0; nb < 8; nb++) {
        int col = wn * 64 + nb * 8 + 2 * tt;
        float2 v0 = make_float2(c[nb][0], c[nb][1]);
        float2 v1 = make_float2(c[nb][2], c[nb][3]);
        if (BIASRELU) {
            float2 b = *reinterpret_cast<const float2*>(bias + col);
            v0.x = fmaxf(v0.x + b.x, 0.f); v0.y = fmaxf(v0.y + b.y, 0.f);
            v1.x = fmaxf(v1.x + b.x, 0.f); v1.y = fmaxf(v1.y + b.y, 0.f);
        }
        *reinterpret_cast<float2*>(Y + (size_t)row0 * DOUT + col) = v0;
        *reinterpret_cast<float2*>(Y + (size_t)(row0 + 8) * DOUT + col) = v1;
    }
}

// ---------------- QKV GEMM (scalar): q,k bf16 (q pre-scaled), v f16 ----------
__global__ void k_gemm_qkv(const float* __restrict__ X, const float* __restrict__ W,
                           const float* __restrict__ bias) {
    constexpr int DIN = 64, DOUT = 192, BR = 16;
    __shared__ float Ws[32 * DOUT];
    constexpr int TX = DOUT / 4;   // 48
    int tx = threadIdx.x;
    int row = blockIdx.x * BR + threadIdx.y;
    float4 acc = make_float4(0.f, 0.f, 0.f, 0.f);
    int t = threadIdx.y * TX + tx;
    constexpr int NTHR = BR * TX;
    float4* Ws4 = reinterpret_cast<float4*>(Ws);

    for (int k0 = 0; k0 < DIN; k0 += 32) {
        for (int idx = t; idx < 8 * DOUT; idx += NTHR) {
            int kk = idx / TX, c4 = idx % TX;
            float4 w;
            w.x = W[(c4 * 4 + 0) * DIN + k0 + kk];
            w.y = W[(c4 * 4 + 1) * DIN + k0 + kk];
            w.z = W[(c4 * 4 + 2) * DIN + k0 + kk];
            w.w = W[(c4 * 4 + 3) * DIN + k0 + kk];
            Ws4[idx] = w;
        }
        __syncthreads();
        const float4* x4 = reinterpret_cast<const float4*>(X + row * DIN + k0);
#pragma unroll
        for (int kk4 = 0; kk4 < 8; kk4++) {
            float4 a = x4[kk4];
            float4 w0 = Ws4[(kk4 * 4 + 0) * TX + tx];
            float4 w1 = Ws4[(kk4 * 4 + 1) * TX + tx];
            float4 w2 = Ws4[(kk4 * 4 + 2) * TX + tx];
            float4 w3 = Ws4[(kk4 * 4 + 3) * TX + tx];
            acc.x += a.x * w0.x; acc.y += a.x * w0.y; acc.z += a.x * w0.z; acc.w += a.x * w0.w;
            acc.x += a.y * w1.x; acc.y += a.y * w1.y; acc.z += a.y * w1.z; acc.w += a.y * w1.w;
            acc.x += a.z * w2.x; acc.y += a.z * w2.y; acc.z += a.z * w2.z; acc.w += a.z * w2.w;
            acc.x += a.w * w3.x; acc.y += a.w * w3.y; acc.z += a.w * w3.z; acc.w += a.w * w3.w;
        }
        __syncthreads();
    }
    float4 b = reinterpret_cast<const float4*>(bias)[tx];
    acc.x += b.x; acc.y += b.y; acc.z += b.z; acc.w += b.w;
    uint p0, p1;
    if (tx < 16) {          // q: fold (1/sqrt(16))*log2(e), bf16
        const float sc = 0.25f * 1.44269504088896340736f;
        acc.x *= sc; acc.y *= sc; acc.z *= sc; acc.w *= sc;
        p0 = cvt_bf16x2(acc.x, acc.y);
        p1 = cvt_bf16x2(acc.z, acc.w);
    } else if (tx < 32) {   // k: bf16
        p0 = cvt_bf16x2(acc.x, acc.y);
        p1 = cvt_bf16x2(acc.z, acc.w);
    } else {                // v: f16 (for f16 PV MMA)
        p0 = cvt_f16x2(acc.x, acc.y);
        p1 = cvt_f16x2(acc.z, acc.w);
    }
    uint2* dst = reinterpret_cast<uint2*>(
        reinterpret_cast<char*>(g_qkvh) + (size_t)row * 384 + tx * 8);
    *dst = make_uint2(p0, p1);
}

// ---------------- GCN aggregation (packed CSR, 4-way MLP batching) ----------
template <int DOUT, bool RELU>
__global__ void k_agg(const float* __restrict__ H, const float* __restrict__ bias,
                      const float* __restrict__ res, float* __restrict__ out) {
    int gw = (blockIdx.x * blockDim.x + threadIdx.x) >> 5;
    int lane = threadIdx.x & 31;
    if (gw >= NN) return;
    int beg = g_rowptr[gw], end = g_rowptr[gw + 1];
    if (DOUT == 128) {
        const float4* H4 = reinterpret_cast<const float4*>(H);
        float4 acc = make_float4(0.f, 0.f, 0.f, 0.f);
        int e = beg;
        for (; e + 4 <= end; e += 4) {
            int2 p0 = g_csr[e + 0], p1 = g_csr[e + 1];
            int2 p2 = g_csr[e + 2], p3 = g_csr[e + 3];
            float4 h0 = H4[p0.x * 32 + lane];
            float4 h1 = H4[p1.x * 32 + lane];
            float4 h2 = H4[p2.x * 32 + lane];
            float4 h3 = H4[p3.x * 32 + lane];
            float w0 = __int_as_float(p0.y), w1 = __int_as_float(p1.y);
            float w2 = __int_as_float(p2.y), w3 = __int_as_float(p3.y);
            acc.x += w0 * h0.x; acc.y += w0 * h0.y; acc.z += w0 * h0.z; acc.w += w0 * h0.w;
            acc.x += w1 * h1.x; acc.y += w1 * h1.y; acc.z += w1 * h1.z; acc.w += w1 * h1.w;
            acc.x += w2 * h2.x; acc.y += w2 * h2.y; acc.z += w2 * h2.z; acc.w += w2 * h2.w;
            acc.x += w3 * h3.x; acc.y += w3 * h3.y; acc.z += w3 * h3.z; acc.w += w3 * h3.w;
        }
        for (; e < end; e++) {
            int2 p = g_csr[e];
            float w = __int_as_float(p.y);
            float4 h = H4[p.x * 32 + lane];
            acc.x += w * h.x; acc.y += w * h.y; acc.z += w * h.z; acc.w += w * h.w;
        }
        float dn = g_dis[gw];
        float d2 = dn * dn;
        float4 h = H4[gw * 32 + lane];
        acc.x += d2 * h.x; acc.y += d2 * h.y; acc.z += d2 * h.z; acc.w += d2 * h.w;
        if (bias != nullptr) {
            float4 b = reinterpret_cast<const float4*>(bias)[lane];
            acc.x += b.x; acc.y += b.y; acc.z += b.z; acc.w += b.w;
        }
        if (RELU) {
            acc.x = fmaxf(acc.x, 0.f); acc.y = fmaxf(acc.y, 0.f);
            acc.z = fmaxf(acc.z, 0.f); acc.w = fmaxf(acc.w, 0.f);
        }
        if (res != nullptr) {
            float4 r = reinterpret_cast<const float4*>(res)[gw * 32 + lane];
            acc.x += r.x; acc.y += r.y; acc.z += r.z; acc.w += r.w;
        }
        reinterpret_cast<float4*>(out)[gw * 32 + lane] = acc;
    } else {  // DOUT == 64
        const float2* H2 = reinterpret_cast<const float2*>(H);
        float2 acc = make_float2(0.f, 0.f);
        int e = beg;
        for (; e + 4 <= end; e += 4) {
            int2 p0 = g_csr[e + 0], p1 = g_csr[e + 1];
            int2 p2 = g_csr[e + 2], p3 = g_csr[e + 3];
            float2 h0 = H2[p0.x * 32 + lane];
            float2 h1 = H2[p1.x * 32 + lane];
            float2 h2 = H2[p2.x * 32 + lane];
            float2 h3 = H2[p3.x * 32 + lane];
            float w0 = __int_as_float(p0.y), w1 = __int_as_float(p1.y);
            float w2 = __int_as_float(p2.y), w3 = __int_as_float(p3.y);
            acc.x += w0 * h0.x; acc.y += w0 * h0.y;
            acc.x += w1 * h1.x; acc.y += w1 * h1.y;
            acc.x += w2 * h2.x; acc.y += w2 * h2.y;
            acc.x += w3 * h3.x; acc.y += w3 * h3.y;
        }
        for (; e < end; e++) {
            int2 p = g_csr[e];
            float w = __int_as_float(p.y);
            float2 h = H2[p.x * 32 + lane];
            acc.x += w * h.x; acc.y += w * h.y;
        }
        float dn = g_dis[gw];
        float d2 = dn * dn;
        float2 h = H2[gw * 32 + lane];
        acc.x += d2 * h.x; acc.y += d2 * h.y;
        if (bias != nullptr) {
            float2 b = reinterpret_cast<const float2*>(bias)[lane];
            acc.x += b.x; acc.y += b.y;
        }
        if (RELU) { acc.x = fmaxf(acc.x, 0.f); acc.y = fmaxf(acc.y, 0.f); }
        if (res != nullptr) {
            float2 r = reinterpret_cast<const float2*>(res)[gw * 32 + lane];
            acc.x += r.x; acc.y += r.y;
        }
        reinterpret_cast<float2*>(out)[gw * 32 + lane] = acc;
    }
}

// ---------------- flash attention: QB=128, dual q-subtile per warp ----------
// CTA: 512 thr = 16 warps; warp w -> head hh=w&3, subtiles sub=w>>2 and sub+4
// (rows sub*16 and 64+sub*16 of the 128-q tile). K/V smem + ldmatrix amortized
// over 2 subtiles -> halved KV L2 traffic vs QB=64. KSPLIT=8 keeps 512 CTAs.
__global__ void __launch_bounds__(512)
k_attn(void) {
    constexpr int KEYS = NN / KSPLIT;        // 1024
    __shared__ __align__(16) __nv_bfloat16 sQ[128 * 72];
    __shared__ __align__(16) __nv_bfloat16 sK[64 * 72];
    __shared__ __align__(16) __nv_bfloat16 sV[64 * 72];

    int t = threadIdx.x;
    int w = t >> 5;
    int l = t & 31;
    int hh = w & 3;
    int sub = w >> 2;
    int qbase = blockIdx.x * 128;
    int kbase = blockIdx.y * KEYS;

    const char* qkvb = reinterpret_cast<const char*>(g_qkvh);

    // --- fill Q tile (128 rows x 128B) ---
    for (int i = t; i < 128 * 8; i += 512) {
        int row = i >> 3, c = i & 7;
        uint4 v = *reinterpret_cast<const uint4*>(qkvb + (size_t)(qbase + row) * 384 + c * 16);
        *reinterpret_cast<uint4*>(reinterpret_cast<char*>(sQ) + row * 144 + c * 16) = v;
    }
    __syncthreads();

    uint sQb = (uint)__cvta_generic_to_shared(sQ);
    uint sKb = (uint)__cvta_generic_to_shared(sK);
    uint sVb = (uint)__cvta_generic_to_shared(sV);

    int r8 = l & 7;
    uint qaddrA = sQb + (sub * 16 + ((l >> 3) & 1) * 8 + r8) * 144 + hh * 32 + ((l >> 4) & 1) * 16;
    uint qaddrB = qaddrA + 64 * 144;
    uint kconst = (((l >> 4) & 1) * 8 + r8) * 144 + hh * 32 + ((l >> 3) & 1) * 16;
    uint vconst = (((l >> 3) & 1) * 8 + r8) * 144 + hh * 32 + ((l >> 4) & 1) * 16;

    uint qa0, qa1, qa2, qa3, qb0, qb1, qb2, qb3;
    ldm4(qa0, qa1, qa2, qa3, qaddrA);
    ldm4(qb0, qb1, qb2, qb3, qaddrB);

    uint onesb = (l < 4) ? 0x3C003C00u : 0u;   // f16 1.0 pairs, ones-column B-frag

    // subtile A accumulators
    float a00 = 0.f, a01 = 0.f, a02 = 0.f, a03 = 0.f;   // dims 0-7
    float a10 = 0.f, a11 = 0.f, a12 = 0.f, a13 = 0.f;   // dims 8-15
    float laA0 = 0.f, laA1 = 0.f, laA2 = 0.f, laA3 = 0.f;
    // subtile B accumulators
    float b00 = 0.f, b01 = 0.f, b02 = 0.f, b03 = 0.f;
    float b10 = 0.f, b11 = 0.f, b12 = 0.f, b13 = 0.f;
    float laB0 = 0.f, laB1 = 0.f, laB2 = 0.f, laB3 = 0.f;

    int lrow = t >> 3, lc = t & 7;
    uint4 kreg, vreg;
    {
        const char* src = qkvb + (size_t)(kbase + lrow) * 384;
        kreg = *reinterpret_cast<const uint4*>(src + 128 + lc * 16);
        vreg = *reinterpret_cast<const uint4*>(src + 256 + lc * 16);
    }

    constexpr int NT = KEYS / 64;            // 16
    for (int tile = 0; tile < NT; tile++) {
        __syncthreads();
        *reinterpret_cast<uint4*>(reinterpret_cast<char*>(sK) + lrow * 144 + lc * 16) = kreg;
        *reinterpret_cast<uint4*>(reinterpret_cast<char*>(sV) + lrow * 144 + lc * 16) = vreg;
        __syncthreads();
        if (tile + 1 < NT) {
            const char* src = qkvb + (size_t)(kbase + (tile + 1) * 64 + lrow) * 384;
            kreg = *reinterpret_cast<const uint4*>(src + 128 + lc * 16);
            vreg = *reinterpret_cast<const uint4*>(src + 256 + lc * 16);
        }
#pragma unroll
        for (int j = 0; j < 64; j += 16) {
            uint k0, k1, k2, k3;
            ldm4(k0, k1, k2, k3, sKb + j * 144 + kconst);
            // subtile A scores
            float s0 = 0.f, s1 = 0.f, s2 = 0.f, s3 = 0.f;
            float u0 = 0.f, u1 = 0.f, u2 = 0.f, u3 = 0.f;
            mma16816_bf16(s0, s1, s2, s3, qa0, qa1, qa2, qa3, k0, k1);
            mma16816_bf16(u0, u1, u2, u3, qa0, qa1, qa2, qa3, k2, k3);
            // subtile B scores
            float y0 = 0.f, y1 = 0.f, y2 = 0.f, y3 = 0.f;
            float z0 = 0.f, z1 = 0.f, z2 = 0.f, z3 = 0.f;
            mma16816_bf16(y0, y1, y2, y3, qb0, qb1, qb2, qb3, k0, k1);
            mma16816_bf16(z0, z1, z2, z3, qb0, qb1, qb2, qb3, k2, k3);

            uint pA0 = ex2_f16x2(cvt_f16x2(s0, s1));
            uint pA1 = ex2_f16x2(cvt_f16x2(s2, s3));
            uint pA2 = ex2_f16x2(cvt_f16x2(u0, u1));
            uint pA3 = ex2_f16x2(cvt_f16x2(u2, u3));
            uint pB0 = ex2_f16x2(cvt_f16x2(y0, y1));
            uint pB1 = ex2_f16x2(cvt_f16x2(y2, y3));
            uint pB2 = ex2_f16x2(cvt_f16x2(z0, z1));
            uint pB3 = ex2_f16x2(cvt_f16x2(z2, z3));

            uint v0, v1, v2, v3;
            ldm4t(v0, v1, v2, v3, sVb + j * 144 + vconst);
            mma16816_f16(a00, a01, a02, a03, pA0, pA1, pA2, pA3, v0, v1);
            mma16816_f16(a10, a11, a12, a13, pA0, pA1, pA2, pA3, v2, v3);
            mma16816_f16(laA0, laA1, laA2, laA3, pA0, pA1, pA2, pA3, onesb, onesb);
            mma16816_f16(b00, b01, b02, b03, pB0, pB1, pB2, pB3, v0, v1);
            mma16816_f16(b10, b11, b12, b13, pB0, pB1, pB2, pB3, v2, v3);
            mma16816_f16(laB0, laB1, laB2, laB3, pB0, pB1, pB2, pB3, onesb, onesb);
        }
    }

    int g = l >> 2, tig = l & 3;
    int split = blockIdx.y;
    // subtile A rows
    {
        int n0 = qbase + sub * 16 + g;
        int n1 = n0 + 8;
        float* base0 = &g_attO[(size_t)(split * NN + n0) * 64 + hh * 16];
        float* base1 = &g_attO[(size_t)(split * NN + n1) * 64 + hh * 16];
        *reinterpret_cast<float2*>(base0 + 2 * tig)     = make_float2(a00, a01);
        *reinterpret_cast<float2*>(base0 + 8 + 2 * tig) = make_float2(a10, a11);
        *reinterpret_cast<float2*>(base1 + 2 * tig)     = make_float2(a02, a03);
        *reinterpret_cast<float2*>(base1 + 8 + 2 * tig) = make_float2(a12, a13);
        if (tig == 0) {
            g_attL[(size_t)(split * NN + n0) * NH + hh] = laA0;
            g_attL[(size_t)(split * NN + n1) * NH + hh] = laA2;
        }
    }
    // subtile B rows (offset +64)
    {
        int n0 = qbase + 64 + sub * 16 + g;
        int n1 = n0 + 8;
        float* base0 = &g_attO[(size_t)(split * NN + n0) * 64 + hh * 16];
        float* base1 = &g_attO[(size_t)(split * NN + n1) * 64 + hh * 16];
        *reinterpret_cast<float2*>(base0 + 2 * tig)     = make_float2(b00, b01);
        *reinterpret_cast<float2*>(base0 + 8 + 2 * tig) = make_float2(b10, b11);
        *reinterpret_cast<float2*>(base1 + 2 * tig)     = make_float2(b02, b03);
        *reinterpret_cast<float2*>(base1 + 8 + 2 * tig) = make_float2(b12, b13);
        if (tig == 0) {
            g_attL[(size_t)(split * NN + n0) * NH + hh] = laB0;
            g_attL[(size_t)(split * NN + n1) * NH + hh] = laB2;
        }
    }
}

// ---------------- fused K-split combine + output projection ------------------
__global__ void __launch_bounds__(512)
k_attn_out(const float* __restrict__ W, const float* __restrict__ bias,
           float* __restrict__ Y) {
    __shared__ float Xs[32 * 64];
    __shared__ float4 Ws4[32 * 16];
    int tx = threadIdx.x;           // 0..15
    int ty = threadIdx.y;           // 0..31
    int t = ty * 16 + tx;
    int nbase = blockIdx.x * 32;

    for (int idx = t; idx < 32 * 64; idx += 512) {
        int nl = idx >> 6;
        int d = idx & 63;
        int n = nbase + nl;
        int hh = d >> 4;
        float o = 0.f, l = 0.f;
#pragma unroll
        for (int s = 0; s < KSPLIT; s++) {
            o += g_attO[(size_t)(s * NN + n) * 64 + d];
            l += g_attL[(size_t)(s * NN + n) * NH + hh];
        }
        Xs[idx] = o / l;
    }

    float4 acc = make_float4(0.f, 0.f, 0.f, 0.f);
    const float4* Xs4 = reinterpret_cast<const float4*>(Xs);
    for (int k0 = 0; k0 < 64; k0 += 32) {
        {
            int kk = ty, c4 = tx;
            float4 wv;
            wv.x = W[(c4 * 4 + 0) * 64 + k0 + kk];
            wv.y = W[(c4 * 4 + 1) * 64 + k0 + kk];
            wv.z = W[(c4 * 4 + 2) * 64 + k0 + kk];
            wv.w = W[(c4 * 4 + 3) * 64 + k0 + kk];
            Ws4[kk * 16 + c4] = wv;
        }
        __syncthreads();
#pragma unroll
        for (int kk4 = 0; kk4 < 8; kk4++) {
            float4 a = Xs4[ty * 16 + (k0 >> 2) + kk4];
            float4 w0 = Ws4[(kk4 * 4 + 0) * 16 + tx];
            float4 w1 = Ws4[(kk4 * 4 + 1) * 16 + tx];
            float4 w2 = Ws4[(kk4 * 4 + 2) * 16 + tx];
            float4 w3 = Ws4[(kk4 * 4 + 3) * 16 + tx];
            acc.x += a.x * w0.x; acc.y += a.x * w0.y; acc.z += a.x * w0.z; acc.w += a.x * w0.w;
            acc.x += a.y * w1.x; acc.y += a.y * w1.y; acc.z += a.y * w1.z; acc.w += a.y * w1.w;
            acc.x += a.z * w2.x; acc.y += a.z * w2.y; acc.z += a.z * w2.z; acc.w += a.z * w2.w;
            acc.x += a.w * w3.x; acc.y += a.w * w3.y; acc.z += a.w * w3.z; acc.w += a.w * w3.w;
        }
        __syncthreads();
    }
    float4 b = reinterpret_cast<const float4*>(bias)[tx];
    acc.x += b.x; acc.y += b.y; acc.z += b.z; acc.w += b.w;
    reinterpret_cast<float4*>(Y + (size_t)(nbase + ty) * 64)[tx] = acc;
}

// ---------------- driver -----------------------------------------------------
extern "C" void kernel_launch(void* const* d_in, const int* in_sizes, int n_in,
                              void* d_out, int out_size) {
    const float* x        = (const float*)d_in[0];
    const int*   ei       = (const int*)d_in[1];
    const float* W_e1 = (const float*)d_in[2];  const float* b_e1 = (const float*)d_in[3];
    const float* W_e2 = (const float*)d_in[4];  const float* b_e2 = (const float*)d_in[5];
    const float* W_e3 = (const float*)d_in[6];  const float* b_e3 = (const float*)d_in[7];
    const float* W_e4 = (const float*)d_in[8];  const float* b_e4 = (const float*)d_in[9];
    const float* W_d1 = (const float*)d_in[10]; const float* b_d1 = (const float*)d_in[11];
    const float* W_d2 = (const float*)d_in[12]; const float* b_d2 = (const float*)d_in[13];
    const float* W_d3 = (const float*)d_in[14]; const float* b_d3 = (const float*)d_in[15];
    const float* W_d4 = (const float*)d_in[16]; const float* b_d4 = (const float*)d_in[17];
    const float* ain_w  = (const float*)d_in[18]; const float* ain_b  = (const float*)d_in[19];
    const float* aout_w = (const float*)d_in[20]; const float* aout_b = (const float*)d_in[21];

    float* out  = (float*)d_out;            // x_recon: NN*64
    float* zout = out + NN * LATD;          // z:       NN*64

    float *pG, *pA, *pB;
    int* pCount;
    __nv_bfloat16 *pWhi, *pWlo;
    cudaGetSymbolAddress((void**)&pG, g_G);
    cudaGetSymbolAddress((void**)&pA, g_bufA);
    cudaGetSymbolAddress((void**)&pB, g_bufB);
    cudaGetSymbolAddress((void**)&pCount, g_count);
    cudaGetSymbolAddress((void**)&pWhi, g_whi);
    cudaGetSymbolAddress((void**)&pWlo, g_wlo);

    // --- CSR build + weight conversion ---
    cudaMemsetAsync(pCount, 0, NN * sizeof(int));
    k_hist<<<EE / 1024, 1024>>>(ei);
    k_wconv<<<(WTOT + 1023) / 1024, 1024>>>(W_e1, W_e2, W_e3, W_e4, W_d1, W_d2, W_d3, W_d4);
    k_scan<<<1, 1024>>>();
    k_build<<<EE / 1024, 1024>>>(ei);

    dim3 gB192(48, 16);

    // --- encoder ---
    // e1 (64->128): agg-first (agg linear): h1 = relu(agg64(x) @ W + b)
    k_agg<64, false><<<NN / 8, 256>>>(x, nullptr, nullptr, pG);
    k_gemm_mma<64, 128, true><<<NN / 64, 256>>>(pG, pWhi + 0, pWlo + 0, b_e1, pA);      // h1
    k_gemm_mma<128, 128, false><<<NN / 64, 256>>>(pA, pWhi + 8192, pWlo + 8192, nullptr, pG);
    k_agg<128, true><<<NN / 8, 256>>>(pG, b_e2, pA, pB);                                // h2
    k_gemm_mma<128, 128, false><<<NN / 64, 256>>>(pB, pWhi + 24576, pWlo + 24576, nullptr, pG);
    k_agg<128, true><<<NN / 8, 256>>>(pG, b_e3, pB, pA);                                // h3
    k_gemm_mma<128, 64, false><<<NN / 128, 256>>>(pA, pWhi + 40960, pWlo + 40960, nullptr, pG);
    k_agg<64, false><<<NN / 8, 256>>>(pG, b_e4, nullptr, zout);                         // z

    // --- attention (bf16 QK / f16 PV mma flash, QB=128) ---
    k_gemm_qkv<<<NN / 16, gB192>>>(zout, ain_w, ain_b);
    k_attn<<<dim3(NN / 128, KSPLIT), 512>>>();
    k_attn_out<<<NN / 32, dim3(16, 32)>>>(aout_w, aout_b, pB);                          // za

    // --- decoder ---
    // d1 (64->128): agg-first: g1 = relu(agg64(za) @ W + b)
    k_agg<64, false><<<NN / 8, 256>>>(pB, nullptr, nullptr, pG);
    k_gemm_mma<64, 128, true><<<NN / 64, 256>>>(pG, pWhi + 49152, pWlo + 49152, b_d1, pA);  // g1
    k_gemm_mma<128, 128, false><<<NN / 64, 256>>>(pA, pWhi + 57344, pWlo + 57344, nullptr, pG);
    k_agg<128, true><<<NN / 8, 256>>>(pG, b_d2, pA, pB);                                // g2
    k_gemm_mma<128, 128, false><<<NN / 64, 256>>>(pB, pWhi + 73728, pWlo + 73728, nullptr, pG);
    k_agg<128, true><<<NN / 8, 256>>>(pG, b_d3, pB, pA);                                // g3
    k_gemm_mma<128, 64, false><<<NN / 128, 256>>>(pA, pWhi + 90112, pWlo + 90112, nullptr, pG);
    k_agg<64, false><<<NN / 8, 256>>>(pG, b_d4, nullptr, out);                          // x_recon
}

// round 17
// speedup vs baseline: 1.0756x; 1.0756x over previous
#include <cuda_runtime.h>
#include <cuda_bf16.h>

#define NN 8192
#define EE 262144
#define FIN 64
#define HIDD 128
#define LATD 64
#define NH 4
#define DHD 16
#define KSPLIT 4

typedef unsigned int uint;

// ---------------- scratch (device globals; no allocations allowed) ----------
__device__ int   g_count[NN];
__device__ int   g_rowptr[NN + 1];
__device__ int   g_fill[NN];
__device__ float g_dis[NN];
__device__ int   g_csr_src[EE];
__device__ float g_csr_norm[EE];

__device__ float g_G[NN * HIDD];     // gemm/agg scratch
__device__ float g_bufA[NN * HIDD];  // ping
__device__ float g_bufB[NN * HIDD];  // pong
__device__ __nv_bfloat16 g_qkvh[NN * 3 * LATD];  // q,k bf16 (q pre-scaled); v f16
__device__ float g_attO[KSPLIT * NN * LATD];     // partial PV sums (raw)
__device__ float g_attL[KSPLIT * NN * NH];       // partial softmax denoms

// pre-converted weights (bf16 split hi/lo), concatenated:
// e1[64x128]@0  e2[128x128]@8192  e3@24576  e4[128x64]@40960
// d1[64x128]@49152  d2@57344  d3@73728  d4[128x64]@90112   total 98304
#define WTOT 98304
__device__ __nv_bfloat16 g_whi[WTOT];
__device__ __nv_bfloat16 g_wlo[WTOT];

// ---------------- fast math helpers ----------------------------------------
__device__ __forceinline__ float fast_rsqrt(float x) {
    float y;
    asm("rsqrt.approx.f32 %0, %1;" : "=f"(y) : "f"(x));
    return y;
}
__device__ __forceinline__ uint cvt_bf16x2(float lo, float hi) {
    uint r;
    asm("cvt.rn.bf16x2.f32 %0, %1, %2;" : "=r"(r) : "f"(hi), "f"(lo));
    return r;
}
__device__ __forceinline__ uint cvt_f16x2(float lo, float hi) {
    uint r;
    asm("cvt.rn.f16x2.f32 %0, %1, %2;" : "=r"(r) : "f"(hi), "f"(lo));
    return r;
}
__device__ __forceinline__ uint ex2_f16x2(uint x) {
    uint y;
    asm("ex2.approx.f16x2 %0, %1;" : "=r"(y) : "r"(x));
    return y;
}

// ---------------- mma / ldmatrix helpers ------------------------------------
__device__ __forceinline__ void ldm4(uint& r0, uint& r1, uint& r2, uint& r3, uint addr) {
    asm volatile("ldmatrix.sync.aligned.m8n8.x4.shared.b16 {%0,%1,%2,%3}, [%4];"
                 : "=r"(r0), "=r"(r1), "=r"(r2), "=r"(r3) : "r"(addr));
}
__device__ __forceinline__ void ldm4t(uint& r0, uint& r1, uint& r2, uint& r3, uint addr) {
    asm volatile("ldmatrix.sync.aligned.m8n8.x4.trans.shared.b16 {%0,%1,%2,%3}, [%4];"
                 : "=r"(r0), "=r"(r1), "=r"(r2), "=r"(r3) : "r"(addr));
}
__device__ __forceinline__ void mma16816_bf16(float& c0, float& c1, float& c2, float& c3,
                                              uint a0, uint a1, uint a2, uint a3,
                                              uint b0, uint b1) {
    asm volatile("mma.sync.aligned.m16n8k16.row.col.f32.bf16.bf16.f32 "
                 "{%0,%1,%2,%3}, {%4,%5,%6,%7}, {%8,%9}, {%0,%1,%2,%3};"
                 : "+f"(c0), "+f"(c1), "+f"(c2), "+f"(c3)
                 : "r"(a0), "r"(a1), "r"(a2), "r"(a3), "r"(b0), "r"(b1));
}
__device__ __forceinline__ void mma16816_f16(float& c0, float& c1, float& c2, float& c3,
                                             uint a0, uint a1, uint a2, uint a3,
                                             uint b0, uint b1) {
    asm volatile("mma.sync.aligned.m16n8k16.row.col.f32.f16.f16.f32 "
                 "{%0,%1,%2,%3}, {%4,%5,%6,%7}, {%8,%9}, {%0,%1,%2,%3};"
                 : "+f"(c0), "+f"(c1), "+f"(c2), "+f"(c3)
                 : "r"(a0), "r"(a1), "r"(a2), "r"(a3), "r"(b0), "r"(b1));
}

// ---------------- CSR build -------------------------------------------------
__global__ void k_hist(const int* __restrict__ ei) {
    int e = blockIdx.x * blockDim.x + threadIdx.x;
    if (e < EE) atomicAdd(&g_count[ei[EE + e]], 1);
}

__global__ void k_scan() {
    __shared__ int s[1024];
    int tid = threadIdx.x;
    int base = tid * 8;
    int local[8];
    int sum = 0;
#pragma unroll
    for (int i = 0; i < 8; i++) { local[i] = g_count[base + i]; sum += local[i]; }
    s[tid] = sum;
    __syncthreads();
    for (int off = 1; off < 1024; off <<= 1) {
        int v = 0;
        if (tid >= off) v = s[tid - off];
        __syncthreads();
        s[tid] += v;
        __syncthreads();
    }
    int run = s[tid] - sum;  // exclusive base
#pragma unroll
    for (int i = 0; i < 8; i++) {
        g_rowptr[base + i] = run;
        g_fill[base + i]   = run;
        g_dis[base + i]    = fast_rsqrt((float)local[i] + 1.0f);
        run += local[i];
    }
    if (tid == 1023) g_rowptr[NN] = run;
}

__global__ void k_build(const int* __restrict__ ei) {
    int e = blockIdx.x * blockDim.x + threadIdx.x;
    if (e < EE) {
        int s = ei[e];
        int d = ei[EE + e];
        int pos = atomicAdd(&g_fill[d], 1);
        g_csr_src[pos]  = s;
        g_csr_norm[pos] = g_dis[s] * g_dis[d];
    }
}

// ---------------- weight conversion: fp32 -> bf16 hi/lo (once per launch) ---
__global__ void k_wconv(const float* __restrict__ w_e1, const float* __restrict__ w_e2,
                        const float* __restrict__ w_e3, const float* __restrict__ w_e4,
                        const float* __restrict__ w_d1, const float* __restrict__ w_d2,
                        const float* __restrict__ w_d3, const float* __restrict__ w_d4) {
    int i = blockIdx.x * blockDim.x + threadIdx.x;
    if (i >= WTOT) return;
    const float* src;
    int off;
    if      (i < 8192)  { src = w_e1; off = 0; }
    else if (i < 24576) { src = w_e2; off = 8192; }
    else if (i < 40960) { src = w_e3; off = 24576; }
    else if (i < 49152) { src = w_e4; off = 40960; }
    else if (i < 57344) { src = w_d1; off = 49152; }
    else if (i < 73728) { src = w_d2; off = 57344; }
    else if (i < 90112) { src = w_d3; off = 73728; }
    else                { src = w_d4; off = 90112; }
    float v = src[i - off];
    __nv_bfloat16 h = __float2bfloat16(v);
    g_whi[i] = h;
    g_wlo[i] = __float2bfloat16(v - __bfloat162float(h));
}

// ---------------- HMMA GEMM: Y = X @ W (+bias+relu), bf16x3 split -----------
// X fp32 -> bf16 hi/lo in smem (A frags, ldm4); W pre-converted bf16 hi/lo in
// global, staged to smem [k][col] and read via ldm4t (B frags). 3 MMAs per n8
// block: hi*hi + hi*lo + lo*hi (fp32 accum) ~ 16-bit effective mantissa.
template <int DIN, int DOUT, bool BIASRELU>
__global__ void __launch_bounds__(256)
k_gemm_mma(const float* __restrict__ X, const __nv_bfloat16* __restrict__ Whi,
           const __nv_bfloat16* __restrict__ Wlo, const float* __restrict__ bias,
           float* __restrict__ Y) {
    constexpr int NWN = DOUT / 64;        // 2 or 1
    constexpr int NWM = 8 / NWN;          // 4 or 8
    constexpr int MT  = NWM * 16;         // 64 or 128
    constexpr int PX  = 80;               // bytes/row of 32-k X chunk (64+16)
    constexpr int PW  = DOUT * 2 + 16;    // 272 or 144

    __shared__ __align__(16) char sXhi[MT * PX];
    __shared__ __align__(16) char sXlo[MT * PX];
    __shared__ __align__(16) char sWhi[32 * PW];
    __shared__ __align__(16) char sWlo[32 * PW];

    int t = threadIdx.x;
    int w = t >> 5, l = t & 31;
    int wm = w % NWM, wn = w / NWM;
    int rowbase = blockIdx.x * MT;

    float c[8][4];
#pragma unroll
    for (int i = 0; i < 8; i++) {
        c[i][0] = 0.f; c[i][1] = 0.f; c[i][2] = 0.f; c[i][3] = 0.f;
    }

    uint sXhiB = (uint)__cvta_generic_to_shared(sXhi);
    uint sXloB = (uint)__cvta_generic_to_shared(sXlo);
    uint sWhiB = (uint)__cvta_generic_to_shared(sWhi);
    uint sWloB = (uint)__cvta_generic_to_shared(sWlo);

    int r8 = l & 7;
    uint aoffc = (uint)(wm * 16 + ((l >> 3) & 1) * 8 + r8) * PX + ((l >> 4) & 1) * 16;
    uint boffc = (uint)(((l >> 3) & 1) * 8 + r8) * PW + wn * 128 + ((l >> 4) & 1) * 16;

    for (int kc = 0; kc < DIN; kc += 32) {
        constexpr int WTASK = 32 * DOUT / 8;
        for (int id = t; id < WTASK; id += 256) {
            int r = id / (DOUT / 8), c8 = id % (DOUT / 8);
            uint4 vh = *reinterpret_cast<const uint4*>(Whi + (kc + r) * DOUT + c8 * 8);
            uint4 vl = *reinterpret_cast<const uint4*>(Wlo + (kc + r) * DOUT + c8 * 8);
            *reinterpret_cast<uint4*>(sWhi + r * PW + c8 * 16) = vh;
            *reinterpret_cast<uint4*>(sWlo + r * PW + c8 * 16) = vl;
        }
        for (int id = t; id < MT * 8; id += 256) {
            int r = id >> 3, g4 = id & 7;
            float4 xv = *reinterpret_cast<const float4*>(X + (size_t)(rowbase + r) * DIN + kc + g4 * 4);
            float h0 = __bfloat162float(__float2bfloat16(xv.x));
            float h1 = __bfloat162float(__float2bfloat16(xv.y));
            float h2 = __bfloat162float(__float2bfloat16(xv.z));
            float h3 = __bfloat162float(__float2bfloat16(xv.w));
            uint2 hp = make_uint2(cvt_bf16x2(xv.x, xv.y), cvt_bf16x2(xv.z, xv.w));
            uint2 lp = make_uint2(cvt_bf16x2(xv.x - h0, xv.y - h1),
                                  cvt_bf16x2(xv.z - h2, xv.w - h3));
            *reinterpret_cast<uint2*>(sXhi + r * PX + g4 * 8) = hp;
            *reinterpret_cast<uint2*>(sXlo + r * PX + g4 * 8) = lp;
        }
        __syncthreads();
#pragma unroll
        for (int ks = 0; ks < 2; ks++) {
            uint ah0, ah1, ah2, ah3, al0, al1, al2, al3;
            ldm4(ah0, ah1, ah2, ah3, sXhiB + aoffc + ks * 32);
            ldm4(al0, al1, al2, al3, sXloB + aoffc + ks * 32);
#pragma unroll
            for (int nb2 = 0; nb2 < 4; nb2++) {
                uint bo = boffc + (uint)ks * 16 * PW + nb2 * 32;
                uint bh0, bh1, bh2, bh3, bl0, bl1, bl2, bl3;
                ldm4t(bh0, bh1, bh2, bh3, sWhiB + bo);
                ldm4t(bl0, bl1, bl2, bl3, sWloB + bo);
                int nb = nb2 * 2;
                mma16816_bf16(c[nb][0], c[nb][1], c[nb][2], c[nb][3],
                              ah0, ah1, ah2, ah3, bh0, bh1);
                mma16816_bf16(c[nb][0], c[nb][1], c[nb][2], c[nb][3],
                              ah0, ah1, ah2, ah3, bl0, bl1);
                mma16816_bf16(c[nb][0], c[nb][1], c[nb][2], c[nb][3],
                              al0, al1, al2, al3, bh0, bh1);
                mma16816_bf16(c[nb + 1][0], c[nb + 1][1], c[nb + 1][2], c[nb + 1][3],
                              ah0, ah1, ah2, ah3, bh2, bh3);
                mma16816_bf16(c[nb + 1][0], c[nb + 1][1], c[nb + 1][2], c[nb + 1][3],
                              ah0, ah1, ah2, ah3, bl2, bl3);
                mma16816_bf16(c[nb + 1][0], c[nb + 1][1], c[nb + 1][2], c[nb + 1][3],
                              al0, al1, al2, al3, bh2, bh3);
            }
        }
        __syncthreads();
    }

    int g = l >> 2, tt = l & 3;
    int row0 = rowbase + wm * 16 + g;
#pragma unroll
    for (int nb = 0; nb < 8; nb++) {
        int col = wn * 64 + nb * 8 + 2 * tt;
        float2 v0 = make_float2(c[nb][0], c[nb][1]);
        float2 v1 = make_float2(c[nb][2], c[nb][3]);
        if (BIASRELU) {
            float2 b = *reinterpret_cast<const float2*>(bias + col);
            v0.x = fmaxf(v0.x + b.x, 0.f); v0.y = fmaxf(v0.y + b.y, 0.f);
            v1.x = fmaxf(v1.x + b.x, 0.f); v1.y = fmaxf(v1.y + b.y, 0.f);
        }
        *reinterpret_cast<float2*>(Y + (size_t)row0 * DOUT + col) = v0;
        *reinterpret_cast<float2*>(Y + (size_t)(row0 + 8) * DOUT + col) = v1;
    }
}

// ---------------- QKV GEMM (scalar): q,k bf16 (q pre-scaled), v f16 ----------
__global__ void k_gemm_qkv(const float* __restrict__ X, const float* __restrict__ W,
                           const float* __restrict__ bias) {
    constexpr int DIN = 64, DOUT = 192, BR = 16;
    __shared__ float Ws[32 * DOUT];
    constexpr int TX = DOUT / 4;   // 48
    int tx = threadIdx.x;
    int row = blockIdx.x * BR + threadIdx.y;
    float4 acc = make_float4(0.f, 0.f, 0.f, 0.f);
    int t = threadIdx.y * TX + tx;
    constexpr int NTHR = BR * TX;
    float4* Ws4 = reinterpret_cast<float4*>(Ws);

    for (int k0 = 0; k0 < DIN; k0 += 32) {
        for (int idx = t; idx < 8 * DOUT; idx += NTHR) {
            int kk = idx / TX, c4 = idx % TX;
            float4 w;
            w.x = W[(c4 * 4 + 0) * DIN + k0 + kk];
            w.y = W[(c4 * 4 + 1) * DIN + k0 + kk];
            w.z = W[(c4 * 4 + 2) * DIN + k0 + kk];
            w.w = W[(c4 * 4 + 3) * DIN + k0 + kk];
            Ws4[idx] = w;
        }
        __syncthreads();
        const float4* x4 = reinterpret_cast<const float4*>(X + row * DIN + k0);
#pragma unroll
        for (int kk4 = 0; kk4 < 8; kk4++) {
            float4 a = x4[kk4];
            float4 w0 = Ws4[(kk4 * 4 + 0) * TX + tx];
            float4 w1 = Ws4[(kk4 * 4 + 1) * TX + tx];
            float4 w2 = Ws4[(kk4 * 4 + 2) * TX + tx];
            float4 w3 = Ws4[(kk4 * 4 + 3) * TX + tx];
            acc.x += a.x * w0.x; acc.y += a.x * w0.y; acc.z += a.x * w0.z; acc.w += a.x * w0.w;
            acc.x += a.y * w1.x; acc.y += a.y * w1.y; acc.z += a.y * w1.z; acc.w += a.y * w1.w;
            acc.x += a.z * w2.x; acc.y += a.z * w2.y; acc.z += a.z * w2.z; acc.w += a.z * w2.w;
            acc.x += a.w * w3.x; acc.y += a.w * w3.y; acc.z += a.w * w3.z; acc.w += a.w * w3.w;
        }
        __syncthreads();
    }
    float4 b = reinterpret_cast<const float4*>(bias)[tx];
    acc.x += b.x; acc.y += b.y; acc.z += b.z; acc.w += b.w;
    uint p0, p1;
    if (tx < 16) {          // q: fold (1/sqrt(16))*log2(e), bf16
        const float sc = 0.25f * 1.44269504088896340736f;
        acc.x *= sc; acc.y *= sc; acc.z *= sc; acc.w *= sc;
        p0 = cvt_bf16x2(acc.x, acc.y);
        p1 = cvt_bf16x2(acc.z, acc.w);
    } else if (tx < 32) {   // k: bf16
        p0 = cvt_bf16x2(acc.x, acc.y);
        p1 = cvt_bf16x2(acc.z, acc.w);
    } else {                // v: f16 (for f16 PV MMA)
        p0 = cvt_f16x2(acc.x, acc.y);
        p1 = cvt_f16x2(acc.z, acc.w);
    }
    uint2* dst = reinterpret_cast<uint2*>(
        reinterpret_cast<char*>(g_qkvh) + (size_t)row * 384 + tx * 8);
    *dst = make_uint2(p0, p1);
}

// ---------------- GCN aggregation (gather over CSR, 4-way MLP batching) ----
template <int DOUT, bool RELU>
__global__ void k_agg(const float* __restrict__ H, const float* __restrict__ bias,
                      const float* __restrict__ res, float* __restrict__ out) {
    int gw = (blockIdx.x * blockDim.x + threadIdx.x) >> 5;
    int lane = threadIdx.x & 31;
    if (gw >= NN) return;
    int beg = g_rowptr[gw], end = g_rowptr[gw + 1];
    if (DOUT == 128) {
        const float4* H4 = reinterpret_cast<const float4*>(H);
        float4 acc = make_float4(0.f, 0.f, 0.f, 0.f);
        int e = beg;
        for (; e + 4 <= end; e += 4) {
            int s0 = g_csr_src[e + 0], s1 = g_csr_src[e + 1];
            int s2 = g_csr_src[e + 2], s3 = g_csr_src[e + 3];
            float w0 = g_csr_norm[e + 0], w1 = g_csr_norm[e + 1];
            float w2 = g_csr_norm[e + 2], w3 = g_csr_norm[e + 3];
            float4 h0 = H4[s0 * 32 + lane];
            float4 h1 = H4[s1 * 32 + lane];
            float4 h2 = H4[s2 * 32 + lane];
            float4 h3 = H4[s3 * 32 + lane];
            acc.x += w0 * h0.x; acc.y += w0 * h0.y; acc.z += w0 * h0.z; acc.w += w0 * h0.w;
            acc.x += w1 * h1.x; acc.y += w1 * h1.y; acc.z += w1 * h1.z; acc.w += w1 * h1.w;
            acc.x += w2 * h2.x; acc.y += w2 * h2.y; acc.z += w2 * h2.z; acc.w += w2 * h2.w;
            acc.x += w3 * h3.x; acc.y += w3 * h3.y; acc.z += w3 * h3.z; acc.w += w3 * h3.w;
        }
        for (; e < end; e++) {
            int s = g_csr_src[e];
            float w = g_csr_norm[e];
            float4 h = H4[s * 32 + lane];
            acc.x += w * h.x; acc.y += w * h.y; acc.z += w * h.z; acc.w += w * h.w;
        }
        float dn = g_dis[gw];
        float d2 = dn * dn;
        float4 h = H4[gw * 32 + lane];
        acc.x += d2 * h.x; acc.y += d2 * h.y; acc.z += d2 * h.z; acc.w += d2 * h.w;
        if (bias != nullptr) {
            float4 b = reinterpret_cast<const float4*>(bias)[lane];
            acc.x += b.x; acc.y += b.y; acc.z += b.z; acc.w += b.w;
        }
        if (RELU) {
            acc.x = fmaxf(acc.x, 0.f); acc.y = fmaxf(acc.y, 0.f);
            acc.z = fmaxf(acc.z, 0.f); acc.w = fmaxf(acc.w, 0.f);
        }
        if (res != nullptr) {
            float4 r = reinterpret_cast<const float4*>(res)[gw * 32 + lane];
            acc.x += r.x; acc.y += r.y; acc.z += r.z; acc.w += r.w;
        }
        reinterpret_cast<float4*>(out)[gw * 32 + lane] = acc;
    } else {  // DOUT == 64
        const float2* H2 = reinterpret_cast<const float2*>(H);
        float2 acc = make_float2(0.f, 0.f);
        int e = beg;
        for (; e + 4 <= end; e += 4) {
            int s0 = g_csr_src[e + 0], s1 = g_csr_src[e + 1];
            int s2 = g_csr_src[e + 2], s3 = g_csr_src[e + 3];
            float w0 = g_csr_norm[e + 0], w1 = g_csr_norm[e + 1];
            float w2 = g_csr_norm[e + 2], w3 = g_csr_norm[e + 3];
            float2 h0 = H2[s0 * 32 + lane];
            float2 h1 = H2[s1 * 32 + lane];
            float2 h2 = H2[s2 * 32 + lane];
            float2 h3 = H2[s3 * 32 + lane];
            acc.x += w0 * h0.x; acc.y += w0 * h0.y;
            acc.x += w1 * h1.x; acc.y += w1 * h1.y;
            acc.x += w2 * h2.x; acc.y += w2 * h2.y;
            acc.x += w3 * h3.x; acc.y += w3 * h3.y;
        }
        for (; e < end; e++) {
            int s = g_csr_src[e];
            float w = g_csr_norm[e];
            float2 h = H2[s * 32 + lane];
            acc.x += w * h.x; acc.y += w * h.y;
        }
        float dn = g_dis[gw];
        float d2 = dn * dn;
        float2 h = H2[gw * 32 + lane];
        acc.x += d2 * h.x; acc.y += d2 * h.y;
        if (bias != nullptr) {
            float2 b = reinterpret_cast<const float2*>(bias)[lane];
            acc.x += b.x; acc.y += b.y;
        }
        if (RELU) { acc.x = fmaxf(acc.x, 0.f); acc.y = fmaxf(acc.y, 0.f); }
        if (res != nullptr) {
            float2 r = reinterpret_cast<const float2*>(res)[gw * 32 + lane];
            acc.x += r.x; acc.y += r.y;
        }
        reinterpret_cast<float2*>(out)[gw * 32 + lane] = acc;
    }
}

// ---------------- flash attention: bf16 QK mma + f16x2 ex2 + f16 PV mma -----
// CTA: 512 thr = 16 warps; warp w -> head hh=w&3, q-subtile sub=w>>2 (16 q).
// Row sums via extra MMA against constant ones-column B-frag (fp32 on tensor
// pipe). Stores UNNORMALIZED O + l; combine does sum(O)/sum(l).
__global__ void __launch_bounds__(512)
k_attn(void) {
    constexpr int KEYS = NN / KSPLIT;
    __shared__ __align__(16) __nv_bfloat16 sQ[64 * 72];
    __shared__ __align__(16) __nv_bfloat16 sK[64 * 72];
    __shared__ __align__(16) __nv_bfloat16 sV[64 * 72];

    int t = threadIdx.x;
    int w = t >> 5;
    int l = t & 31;
    int hh = w & 3;
    int sub = w >> 2;
    int qbase = blockIdx.x * 64;
    int kbase = blockIdx.y * KEYS;

    const char* qkvb = reinterpret_cast<const char*>(g_qkvh);

    {
        int row = t >> 3, c = t & 7;
        uint4 v = *reinterpret_cast<const uint4*>(qkvb + (size_t)(qbase + row) * 384 + c * 16);
        *reinterpret_cast<uint4*>(reinterpret_cast<char*>(sQ) + row * 144 + c * 16) = v;
    }
    __syncthreads();

    uint sQb = (uint)__cvta_generic_to_shared(sQ);
    uint sKb = (uint)__cvta_generic_to_shared(sK);
    uint sVb = (uint)__cvta_generic_to_shared(sV);

    int r8 = l & 7;
    uint qaddr = sQb + (sub * 16 + ((l >> 3) & 1) * 8 + r8) * 144 + hh * 32 + ((l >> 4) & 1) * 16;
    uint kconst = (((l >> 4) & 1) * 8 + r8) * 144 + hh * 32 + ((l >> 3) & 1) * 16;
    uint vconst = (((l >> 3) & 1) * 8 + r8) * 144 + hh * 32 + ((l >> 4) & 1) * 16;

    uint qa0, qa1, qa2, qa3;
    ldm4(qa0, qa1, qa2, qa3, qaddr);

    uint onesb = (l < 4) ? 0x3C003C00u : 0u;   // f16 1.0 pairs, ones-column B-frag

    float o00 = 0.f, o01 = 0.f, o02 = 0.f, o03 = 0.f;   // dims 0-7
    float o10 = 0.f, o11 = 0.f, o12 = 0.f, o13 = 0.f;   // dims 8-15
    float la0 = 0.f, la1 = 0.f, la2 = 0.f, la3 = 0.f;   // row sums

    int lrow = t >> 3, lc = t & 7;
    uint4 kreg, vreg;
    {
        const char* src = qkvb + (size_t)(kbase + lrow) * 384;
        kreg = *reinterpret_cast<const uint4*>(src + 128 + lc * 16);
        vreg = *reinterpret_cast<const uint4*>(src + 256 + lc * 16);
    }

    constexpr int NT = KEYS / 64;
    for (int tile = 0; tile < NT; tile++) {
        __syncthreads();
        *reinterpret_cast<uint4*>(reinterpret_cast<char*>(sK) + lrow * 144 + lc * 16) = kreg;
        *reinterpret_cast<uint4*>(reinterpret_cast<char*>(sV) + lrow * 144 + lc * 16) = vreg;
        __syncthreads();
        if (tile + 1 < NT) {
            const char* src = qkvb + (size_t)(kbase + (tile + 1) * 64 + lrow) * 384;
            kreg = *reinterpret_cast<const uint4*>(src + 128 + lc * 16);
            vreg = *reinterpret_cast<const uint4*>(src + 256 + lc * 16);
        }
#pragma unroll
        for (int j = 0; j < 64; j += 16) {
            uint k0, k1, k2, k3;
            ldm4(k0, k1, k2, k3, sKb + j * 144 + kconst);
            float s0 = 0.f, s1 = 0.f, s2 = 0.f, s3 = 0.f;
            float u0 = 0.f, u1 = 0.f, u2 = 0.f, u3 = 0.f;
            mma16816_bf16(s0, s1, s2, s3, qa0, qa1, qa2, qa3, k0, k1);
            mma16816_bf16(u0, u1, u2, u3, qa0, qa1, qa2, qa3, k2, k3);
            uint pa0 = ex2_f16x2(cvt_f16x2(s0, s1));
            uint pa1 = ex2_f16x2(cvt_f16x2(s2, s3));
            uint pa2 = ex2_f16x2(cvt_f16x2(u0, u1));
            uint pa3 = ex2_f16x2(cvt_f16x2(u2, u3));
            uint v0, v1, v2, v3;
            ldm4t(v0, v1, v2, v3, sVb + j * 144 + vconst);
            mma16816_f16(o00, o01, o02, o03, pa0, pa1, pa2, pa3, v0, v1);
            mma16816_f16(o10, o11, o12, o13, pa0, pa1, pa2, pa3, v2, v3);
            mma16816_f16(la0, la1, la2, la3, pa0, pa1, pa2, pa3, onesb, onesb);
        }
    }

    int g = l >> 2, tig = l & 3;
    int n0 = qbase + sub * 16 + g;
    int n1 = n0 + 8;
    int split = blockIdx.y;

    float* base0 = &g_attO[(size_t)(split * NN + n0) * 64 + hh * 16];
    float* base1 = &g_attO[(size_t)(split * NN + n1) * 64 + hh * 16];
    *reinterpret_cast<float2*>(base0 + 2 * tig)     = make_float2(o00, o01);
    *reinterpret_cast<float2*>(base0 + 8 + 2 * tig) = make_float2(o10, o11);
    *reinterpret_cast<float2*>(base1 + 2 * tig)     = make_float2(o02, o03);
    *reinterpret_cast<float2*>(base1 + 8 + 2 * tig) = make_float2(o12, o13);
    if (tig == 0) {
        g_attL[(size_t)(split * NN + n0) * NH + hh] = la0;
        g_attL[(size_t)(split * NN + n1) * NH + hh] = la2;
    }
}

// ---------------- fused K-split combine + output projection ------------------
__global__ void __launch_bounds__(512)
k_attn_out(const float* __restrict__ W, const float* __restrict__ bias,
           float* __restrict__ Y) {
    __shared__ float Xs[32 * 64];
    __shared__ float4 Ws4[32 * 16];
    int tx = threadIdx.x;           // 0..15
    int ty = threadIdx.y;           // 0..31
    int t = ty * 16 + tx;
    int nbase = blockIdx.x * 32;

    for (int idx = t; idx < 32 * 64; idx += 512) {
        int nl = idx >> 6;
        int d = idx & 63;
        int n = nbase + nl;
        int hh = d >> 4;
        float o = 0.f, l = 0.f;
#pragma unroll
        for (int s = 0; s < KSPLIT; s++) {
            o += g_attO[(size_t)(s * NN + n) * 64 + d];
            l += g_attL[(size_t)(s * NN + n) * NH + hh];
        }
        Xs[idx] = o / l;
    }

    float4 acc = make_float4(0.f, 0.f, 0.f, 0.f);
    const float4* Xs4 = reinterpret_cast<const float4*>(Xs);
    for (int k0 = 0; k0 < 64; k0 += 32) {
        {
            int kk = ty, c4 = tx;
            float4 wv;
            wv.x = W[(c4 * 4 + 0) * 64 + k0 + kk];
            wv.y = W[(c4 * 4 + 1) * 64 + k0 + kk];
            wv.z = W[(c4 * 4 + 2) * 64 + k0 + kk];
            wv.w = W[(c4 * 4 + 3) * 64 + k0 + kk];
            Ws4[kk * 16 + c4] = wv;
        }
        __syncthreads();
#pragma unroll
        for (int kk4 = 0; kk4 < 8; kk4++) {
            float4 a = Xs4[ty * 16 + (k0 >> 2) + kk4];
            float4 w0 = Ws4[(kk4 * 4 + 0) * 16 + tx];
            float4 w1 = Ws4[(kk4 * 4 + 1) * 16 + tx];
            float4 w2 = Ws4[(kk4 * 4 + 2) * 16 + tx];
            float4 w3 = Ws4[(kk4 * 4 + 3) * 16 + tx];
            acc.x += a.x * w0.x; acc.y += a.x * w0.y; acc.z += a.x * w0.z; acc.w += a.x * w0.w;
            acc.x += a.y * w1.x; acc.y += a.y * w1.y; acc.z += a.y * w1.z; acc.w += a.y * w1.w;
            acc.x += a.z * w2.x; acc.y += a.z * w2.y; acc.z += a.z * w2.z; acc.w += a.z * w2.w;
            acc.x += a.w * w3.x; acc.y += a.w * w3.y; acc.z += a.w * w3.z; acc.w += a.w * w3.w;
        }
        __syncthreads();
    }
    float4 b = reinterpret_cast<const float4*>(bias)[tx];
    acc.x += b.x; acc.y += b.y; acc.z += b.z; acc.w += b.w;
    reinterpret_cast<float4*>(Y + (size_t)(nbase + ty) * 64)[tx] = acc;
}

// ---------------- driver -----------------------------------------------------
extern "C" void kernel_launch(void* const* d_in, const int* in_sizes, int n_in,
                              void* d_out, int out_size) {
    const float* x        = (const float*)d_in[0];
    const int*   ei       = (const int*)d_in[1];
    const float* W_e1 = (const float*)d_in[2];  const float* b_e1 = (const float*)d_in[3];
    const float* W_e2 = (const float*)d_in[4];  const float* b_e2 = (const float*)d_in[5];
    const float* W_e3 = (const float*)d_in[6];  const float* b_e3 = (const float*)d_in[7];
    const float* W_e4 = (const float*)d_in[8];  const float* b_e4 = (const float*)d_in[9];
    const float* W_d1 = (const float*)d_in[10]; const float* b_d1 = (const float*)d_in[11];
    const float* W_d2 = (const float*)d_in[12]; const float* b_d2 = (const float*)d_in[13];
    const float* W_d3 = (const float*)d_in[14]; const float* b_d3 = (const float*)d_in[15];
    const float* W_d4 = (const float*)d_in[16]; const float* b_d4 = (const float*)d_in[17];
    const float* ain_w  = (const float*)d_in[18]; const float* ain_b  = (const float*)d_in[19];
    const float* aout_w = (const float*)d_in[20]; const float* aout_b = (const float*)d_in[21];

    float* out  = (float*)d_out;            // x_recon: NN*64
    float* zout = out + NN * LATD;          // z:       NN*64

    float *pG, *pA, *pB;
    int* pCount;
    __nv_bfloat16 *pWhi, *pWlo;
    cudaGetSymbolAddress((void**)&pG, g_G);
    cudaGetSymbolAddress((void**)&pA, g_bufA);
    cudaGetSymbolAddress((void**)&pB, g_bufB);
    cudaGetSymbolAddress((void**)&pCount, g_count);
    cudaGetSymbolAddress((void**)&pWhi, g_whi);
    cudaGetSymbolAddress((void**)&pWlo, g_wlo);

    // --- CSR build + weight conversion ---
    cudaMemsetAsync(pCount, 0, NN * sizeof(int));
    k_hist<<<EE / 1024, 1024>>>(ei);
    k_wconv<<<(WTOT + 1023) / 1024, 1024>>>(W_e1, W_e2, W_e3, W_e4, W_d1, W_d2, W_d3, W_d4);
    k_scan<<<1, 1024>>>();
    k_build<<<EE / 1024, 1024>>>(ei);

    dim3 gB192(48, 16);

    // --- encoder ---
    // e1 (64->128): agg-first (agg linear): h1 = relu(agg64(x) @ W + b)
    k_agg<64, false><<<NN / 8, 256>>>(x, nullptr, nullptr, pG);
    k_gemm_mma<64, 128, true><<<NN / 64, 256>>>(pG, pWhi + 0, pWlo + 0, b_e1, pA);      // h1
    k_gemm_mma<128, 128, false><<<NN / 64, 256>>>(pA, pWhi + 8192, pWlo + 8192, nullptr, pG);
    k_agg<128, true><<<NN / 8, 256>>>(pG, b_e2, pA, pB);                                // h2
    k_gemm_mma<128, 128, false><<<NN / 64, 256>>>(pB, pWhi + 24576, pWlo + 24576, nullptr, pG);
    k_agg<128, true><<<NN / 8, 256>>>(pG, b_e3, pB, pA);                                // h3
    k_gemm_mma<128, 64, false><<<NN / 128, 256>>>(pA, pWhi + 40960, pWlo + 40960, nullptr, pG);
    k_agg<64, false><<<NN / 8, 256>>>(pG, b_e4, nullptr, zout);                         // z

    // --- attention (bf16 QK / f16 PV mma flash) ---
    k_gemm_qkv<<<NN / 16, gB192>>>(zout, ain_w, ain_b);
    k_attn<<<dim3(NN / 64, KSPLIT), 512>>>();
    k_attn_out<<<NN / 32, dim3(16, 32)>>>(aout_w, aout_b, pB);                          // za

    // --- decoder ---
    // d1 (64->128): agg-first: g1 = relu(agg64(za) @ W + b)
    k_agg<64, false><<<NN / 8, 256>>>(pB, nullptr, nullptr, pG);
    k_gemm_mma<64, 128, true><<<NN / 64, 256>>>(pG, pWhi + 49152, pWlo + 49152, b_d1, pA);  // g1
    k_gemm_mma<128, 128, false><<<NN / 64, 256>>>(pA, pWhi + 57344, pWlo + 57344, nullptr, pG);
    k_agg<128, true><<<NN / 8, 256>>>(pG, b_d2, pA, pB);                                // g2
    k_gemm_mma<128, 128, false><<<NN / 64, 256>>>(pB, pWhi + 73728, pWlo + 73728, nullptr, pG);
    k_agg<128, true><<<NN / 8, 256>>>(pG, b_d3, pB, pA);                                // g3
    k_gemm_mma<128, 64, false><<<NN / 128, 256>>>(pA, pWhi + 90112, pWlo + 90112, nullptr, pG);
    k_agg<64, false><<<NN / 8, 256>>>(pG, b_d4, nullptr, out);                          // x_recon
}